// round 1
// baseline (speedup 1.0000x reference)
#include <cuda_runtime.h>
#include <math.h>

// ---------------------------------------------------------------------------
// Problem constants
// ---------------------------------------------------------------------------
#define S_LEN  2048
#define HID    2560
#define QKV_N  3072          // NH*D + 2*NKV*D = 2560 + 256 + 256
#define NPAIR  20            // NH/2
#define SCALE_F 0.125f       // 1/sqrt(64)

// ---------------------------------------------------------------------------
// Scratch (no allocations allowed -> __device__ globals)
// ---------------------------------------------------------------------------
__device__ float g_qkv [S_LEN * QKV_N];   // QKV projection output
__device__ float g_O1  [S_LEN * HID];     // path-1 attention out [s, p*128+c]
__device__ float g_O2  [S_LEN * HID];     // path-2 attention out
__device__ float g_attn[S_LEN * HID];     // combined + rmsnormed
__device__ float g_lambda;                // lambda_full

// ---------------------------------------------------------------------------
// Generic SGEMM: C[M,N] = A[M,K] @ B[N,K]^T + bias[N]
// 128x128 block, BK=16, 256 threads, 8x8 microtile
// ---------------------------------------------------------------------------
template<int BM, int BN, int BK>
__global__ __launch_bounds__(256)
void sgemm_bias(const float* __restrict__ A, const float* __restrict__ B,
                const float* __restrict__ bias, float* __restrict__ C,
                int M, int N, int K)
{
    __shared__ float As[BK * BM];
    __shared__ float Bs[BK * BN];

    const int tid = threadIdx.x;
    const int tx  = tid & 15;
    const int ty  = tid >> 4;
    const int bm  = blockIdx.y * BM;
    const int bn  = blockIdx.x * BN;

    float acc[8][8];
#pragma unroll
    for (int i = 0; i < 8; i++)
#pragma unroll
        for (int j = 0; j < 8; j++) acc[i][j] = 0.f;

    for (int k0 = 0; k0 < K; k0 += BK) {
        // Load A tile (BM x BK), store transposed As[k][m]
#pragma unroll
        for (int it = 0; it < (BM * BK / 4) / 256; it++) {
            int lin = it * 256 + tid;          // 0..511
            int row = lin >> 2;                // 0..127
            int c4  = (lin & 3) << 2;          // 0,4,8,12
            float4 v = *(const float4*)(A + (size_t)(bm + row) * K + k0 + c4);
            As[(c4 + 0) * BM + row] = v.x;
            As[(c4 + 1) * BM + row] = v.y;
            As[(c4 + 2) * BM + row] = v.z;
            As[(c4 + 3) * BM + row] = v.w;
        }
        // Load B tile (BN x BK), store transposed Bs[k][n]
#pragma unroll
        for (int it = 0; it < (BN * BK / 4) / 256; it++) {
            int lin = it * 256 + tid;
            int row = lin >> 2;
            int c4  = (lin & 3) << 2;
            float4 v = *(const float4*)(B + (size_t)(bn + row) * K + k0 + c4);
            Bs[(c4 + 0) * BN + row] = v.x;
            Bs[(c4 + 1) * BN + row] = v.y;
            Bs[(c4 + 2) * BN + row] = v.z;
            Bs[(c4 + 3) * BN + row] = v.w;
        }
        __syncthreads();

#pragma unroll
        for (int kk = 0; kk < BK; kk++) {
            float a[8], b[8];
            *(float4*)(a)     = *(float4*)(As + kk * BM + ty * 8);
            *(float4*)(a + 4) = *(float4*)(As + kk * BM + ty * 8 + 4);
            *(float4*)(b)     = *(float4*)(Bs + kk * BN + tx * 8);
            *(float4*)(b + 4) = *(float4*)(Bs + kk * BN + tx * 8 + 4);
#pragma unroll
            for (int i = 0; i < 8; i++)
#pragma unroll
                for (int j = 0; j < 8; j++)
                    acc[i][j] += a[i] * b[j];
        }
        __syncthreads();
    }

#pragma unroll
    for (int i = 0; i < 8; i++) {
        int row = bm + ty * 8 + i;
#pragma unroll
        for (int j = 0; j < 8; j += 4) {
            int col = bn + tx * 8 + j;
            float4 bv = *(const float4*)(bias + col);
            float4 o;
            o.x = acc[i][j + 0] + bv.x;
            o.y = acc[i][j + 1] + bv.y;
            o.z = acc[i][j + 2] + bv.z;
            o.w = acc[i][j + 3] + bv.w;
            *(float4*)(C + (size_t)row * N + col) = o;
        }
    }
}

// ---------------------------------------------------------------------------
// Flash attention (fp32 SIMT). One block = 64 queries x one pair-head x one path.
// Dq = 64, Dv = 128 (v1|v2 contiguous in qkv). Online softmax.
// Thread layout: 16x16, S microtile 4x4 with rows {ty+16*ii}, cols {tx+16*jj};
// O microtile 4x8 rows {ty+16*ii}, cols {tx*8 .. tx*8+7}.
// ---------------------------------------------------------------------------
#define QSTR 68      // stride for Q and K tiles (2-way LDS conflict max)
#define VSTR 128     // V reads are tx-contiguous -> conflict-free
#define SSTR 65      // scalar access only
#define ATT_SMEM ((64 * QSTR + 64 * VSTR + 64 * SSTR) * 4)

__global__ __launch_bounds__(256)
void attn_kernel(const float* __restrict__ qkv,
                 float* __restrict__ O1, float* __restrict__ O2)
{
    extern __shared__ float sm[];
    float* Qs  = sm;                    // 64 * QSTR
    float* KVs = sm + 64 * QSTR;        // 64 * VSTR (also used for K)
    float* Ss  = KVs + 64 * VSTR;       // 64 * SSTR

    const int tid = threadIdx.x;
    const int tx  = tid & 15;
    const int ty  = tid >> 4;
    const int i0  = blockIdx.x * 64;
    const int p   = blockIdx.y;
    const int pt  = blockIdx.z;
    const int h   = 2 * p + pt;
    const int gp  = p / 10;
    const int qoff = h * 64;
    const int koff = 2560 + (2 * gp + pt) * 64;
    const int voff = 2816 + 2 * gp * 64;        // 128 contiguous floats (v1|v2)
    float* Oout = pt ? O2 : O1;

    // Load Q tile (64x64), pre-scaled by 1/sqrt(D)
#pragma unroll
    for (int it = 0; it < 4; it++) {
        int lin = it * 256 + tid;       // 0..1023
        int row = lin >> 4;             // 0..63
        int c4  = (lin & 15) << 2;      // 0..60
        float4 v = *(const float4*)(qkv + (size_t)(i0 + row) * QKV_N + qoff + c4);
        v.x *= SCALE_F; v.y *= SCALE_F; v.z *= SCALE_F; v.w *= SCALE_F;
        *(float4*)(Qs + row * QSTR + c4) = v;
    }

    float m[4], l[4], o[4][8];
#pragma unroll
    for (int i = 0; i < 4; i++) {
        m[i] = -1e30f; l[i] = 0.f;
#pragma unroll
        for (int j = 0; j < 8; j++) o[i][j] = 0.f;
    }

    for (int j0 = 0; j0 <= i0; j0 += 64) {
        __syncthreads();    // protect KVs (prev PV reads) + Ss
        // Load K tile (64x64) into KVs with stride QSTR
#pragma unroll
        for (int it = 0; it < 4; it++) {
            int lin = it * 256 + tid;
            int row = lin >> 4;
            int c4  = (lin & 15) << 2;
            float4 v = *(const float4*)(qkv + (size_t)(j0 + row) * QKV_N + koff + c4);
            *(float4*)(KVs + row * QSTR + c4) = v;
        }
        __syncthreads();

        // S = Q K^T  (4x4 per thread)
        float s[4][4];
#pragma unroll
        for (int i = 0; i < 4; i++)
#pragma unroll
            for (int j = 0; j < 4; j++) s[i][j] = 0.f;

#pragma unroll
        for (int d = 0; d < 64; d += 4) {
            float4 qv[4], kv[4];
#pragma unroll
            for (int ii = 0; ii < 4; ii++)
                qv[ii] = *(float4*)(Qs + (ty + 16 * ii) * QSTR + d);
#pragma unroll
            for (int jj = 0; jj < 4; jj++)
                kv[jj] = *(float4*)(KVs + (tx + 16 * jj) * QSTR + d);
#pragma unroll
            for (int ii = 0; ii < 4; ii++)
#pragma unroll
                for (int jj = 0; jj < 4; jj++)
                    s[ii][jj] += qv[ii].x * kv[jj].x + qv[ii].y * kv[jj].y
                               + qv[ii].z * kv[jj].z + qv[ii].w * kv[jj].w;
        }

        // Causal mask on the diagonal block
        if (j0 == i0) {
#pragma unroll
            for (int ii = 0; ii < 4; ii++) {
                int gi = ty + 16 * ii;
#pragma unroll
                for (int jj = 0; jj < 4; jj++) {
                    int gj = tx + 16 * jj;
                    if (gj > gi) s[ii][jj] = -1e30f;
                }
            }
        }

        // Online softmax per row (rows distributed over ii; cols over tx,jj)
#pragma unroll
        for (int ii = 0; ii < 4; ii++) {
            float tm = fmaxf(fmaxf(s[ii][0], s[ii][1]), fmaxf(s[ii][2], s[ii][3]));
#pragma unroll
            for (int off = 1; off < 16; off <<= 1)
                tm = fmaxf(tm, __shfl_xor_sync(0xffffffffu, tm, off));
            float mn = fmaxf(m[ii], tm);
            float sc = __expf(m[ii] - mn);
            float rs = 0.f;
#pragma unroll
            for (int jj = 0; jj < 4; jj++) {
                float e = __expf(s[ii][jj] - mn);
                s[ii][jj] = e;
                rs += e;
            }
#pragma unroll
            for (int off = 1; off < 16; off <<= 1)
                rs += __shfl_xor_sync(0xffffffffu, rs, off);
            l[ii] = l[ii] * sc + rs;
            m[ii] = mn;
#pragma unroll
            for (int j = 0; j < 8; j++) o[ii][j] *= sc;
            // stash P
#pragma unroll
            for (int jj = 0; jj < 4; jj++)
                Ss[(ty + 16 * ii) * SSTR + tx + 16 * jj] = s[ii][jj];
        }
        __syncthreads();    // K reads done, P written -> load V

        // Load V tile (64x128) into KVs with stride VSTR
#pragma unroll
        for (int it = 0; it < 8; it++) {
            int lin = it * 256 + tid;       // 0..2047
            int row = lin >> 5;             // 0..63
            int c4  = (lin & 31) << 2;      // 0..124
            float4 v = *(const float4*)(qkv + (size_t)(j0 + row) * QKV_N + voff + c4);
            *(float4*)(KVs + row * VSTR + c4) = v;
        }
        __syncthreads();

        // O += P @ V
#pragma unroll 8
        for (int kk = 0; kk < 64; kk++) {
            float pv[4];
#pragma unroll
            for (int ii = 0; ii < 4; ii++)
                pv[ii] = Ss[(ty + 16 * ii) * SSTR + kk];
            float4 va = *(float4*)(KVs + kk * VSTR + tx * 8);
            float4 vb = *(float4*)(KVs + kk * VSTR + tx * 8 + 4);
#pragma unroll
            for (int ii = 0; ii < 4; ii++) {
                o[ii][0] += pv[ii] * va.x;
                o[ii][1] += pv[ii] * va.y;
                o[ii][2] += pv[ii] * va.z;
                o[ii][3] += pv[ii] * va.w;
                o[ii][4] += pv[ii] * vb.x;
                o[ii][5] += pv[ii] * vb.y;
                o[ii][6] += pv[ii] * vb.z;
                o[ii][7] += pv[ii] * vb.w;
            }
        }
    }

    // Epilogue: normalize and store
#pragma unroll
    for (int ii = 0; ii < 4; ii++) {
        float inv = 1.f / l[ii];
        int row = i0 + ty + 16 * ii;
        float* dst = Oout + (size_t)row * HID + p * 128 + tx * 8;
        float4 a, b2;
        a.x = o[ii][0] * inv; a.y = o[ii][1] * inv;
        a.z = o[ii][2] * inv; a.w = o[ii][3] * inv;
        b2.x = o[ii][4] * inv; b2.y = o[ii][5] * inv;
        b2.z = o[ii][6] * inv; b2.w = o[ii][7] * inv;
        *(float4*)(dst)     = a;
        *(float4*)(dst + 4) = b2;
    }
}

// ---------------------------------------------------------------------------
// lambda_full = exp(sum lq1*lk1) - exp(sum lq2*lk2) + LAMBDA_INIT
// ---------------------------------------------------------------------------
__global__ void lambda_kernel(const float* __restrict__ lq1, const float* __restrict__ lk1,
                              const float* __restrict__ lq2, const float* __restrict__ lk2)
{
    __shared__ float sa[64], sb[64];
    int t = threadIdx.x;
    sa[t] = lq1[t] * lk1[t];
    sb[t] = lq2[t] * lk2[t];
    __syncthreads();
    if (t == 0) {
        float s1 = 0.f, s2 = 0.f;
        for (int i = 0; i < 64; i++) { s1 += sa[i]; s2 += sb[i]; }
        const float lambda_init = 0.8f - 0.6f * expf(-0.3f * 17.0f);
        g_lambda = expf(s1) - expf(s2) + lambda_init;
    }
}

// ---------------------------------------------------------------------------
// Combine: a = O1 - lambda*O2 ; rmsnorm over 128 dims ; * subln_w * (1-l_init)
// One block per (s, p); 128 threads, one column each.
// ---------------------------------------------------------------------------
__global__ __launch_bounds__(128)
void combine_kernel(const float* __restrict__ O1, const float* __restrict__ O2,
                    const float* __restrict__ subln, float* __restrict__ Aout)
{
    const int sp = blockIdx.x;          // 0 .. S_LEN*NPAIR-1
    const int s  = sp / NPAIR;
    const int pp = sp - s * NPAIR;
    const int c  = threadIdx.x;         // 0..127
    const size_t idx = (size_t)s * HID + pp * 128 + c;

    const float lam = g_lambda;
    const float a = O1[idx] - lam * O2[idx];

    float ss = a * a;
#pragma unroll
    for (int off = 16; off > 0; off >>= 1)
        ss += __shfl_xor_sync(0xffffffffu, ss, off);

    __shared__ float ws[4];
    __shared__ float tot;
    if ((c & 31) == 0) ws[c >> 5] = ss;
    __syncthreads();
    if (c == 0) tot = ws[0] + ws[1] + ws[2] + ws[3];
    __syncthreads();

    const float lambda_init = 0.8f - 0.6f * expf(-0.3f * 17.0f);
    const float rms = rsqrtf(tot * (1.f / 128.f) + 1e-5f);
    Aout[idx] = subln[c] * a * rms * (1.f - lambda_init);
}

// ---------------------------------------------------------------------------
// Launch
// ---------------------------------------------------------------------------
extern "C" void kernel_launch(void* const* d_in, const int* in_sizes, int n_in,
                              void* d_out, int out_size)
{
    const float* hidden = (const float*)d_in[0];
    const float* Wqkv_w = (const float*)d_in[1];
    const float* Wqkv_b = (const float*)d_in[2];
    const float* out_w  = (const float*)d_in[3];
    const float* out_b  = (const float*)d_in[4];
    const float* lq1    = (const float*)d_in[5];
    const float* lk1    = (const float*)d_in[6];
    const float* lq2    = (const float*)d_in[7];
    const float* lk2    = (const float*)d_in[8];
    const float* subln  = (const float*)d_in[9];
    float* out = (float*)d_out;

    float *qkv, *O1, *O2, *attn;
    cudaGetSymbolAddress((void**)&qkv,  g_qkv);
    cudaGetSymbolAddress((void**)&O1,   g_O1);
    cudaGetSymbolAddress((void**)&O2,   g_O2);
    cudaGetSymbolAddress((void**)&attn, g_attn);

    cudaFuncSetAttribute(attn_kernel,
                         cudaFuncAttributeMaxDynamicSharedMemorySize, ATT_SMEM);

    // 1) QKV projection: [2048,3072] = hidden @ Wqkv_w^T + b
    {
        dim3 grid(QKV_N / 128, S_LEN / 128);
        sgemm_bias<128, 128, 16><<<grid, 256>>>(hidden, Wqkv_w, Wqkv_b, qkv,
                                                S_LEN, QKV_N, HID);
    }

    // 2) lambda scalar
    lambda_kernel<<<1, 64>>>(lq1, lk1, lq2, lk2);

    // 3) Flash attention: both paths, all 20 pair-heads
    {
        dim3 grid(S_LEN / 64, NPAIR, 2);
        attn_kernel<<<grid, 256, ATT_SMEM>>>(qkv, O1, O2);
    }

    // 4) Differential combine + RMSNorm
    combine_kernel<<<S_LEN * NPAIR, 128>>>(O1, O2, subln, attn);

    // 5) Output projection: [2048,2560] = attn @ out_w^T + b
    {
        dim3 grid(HID / 128, S_LEN / 128);
        sgemm_bias<128, 128, 16><<<grid, 256>>>(attn, out_w, out_b, out,
                                                S_LEN, HID, HID);
    }
}

// round 4
// speedup vs baseline: 3.2982x; 3.2982x over previous
#include <cuda_runtime.h>
#include <math.h>

// ---------------------------------------------------------------------------
// Problem constants
// ---------------------------------------------------------------------------
#define S_LEN  2048
#define HID    2560
#define QKV_N  3072          // NH*D + 2*NKV*D = 2560 + 256 + 256
#define NPAIR  20            // NH/2
#define SCALE_F 0.125f       // 1/sqrt(64)

// ---------------------------------------------------------------------------
// Scratch (no allocations allowed -> __device__ globals)
// ---------------------------------------------------------------------------
__device__ float g_qkv [S_LEN * QKV_N];
__device__ float g_O1  [S_LEN * HID];
__device__ float g_O2  [S_LEN * HID];
__device__ float g_attn[S_LEN * HID];
__device__ float g_lambda;

// ---------------------------------------------------------------------------
// tf32 helpers
// ---------------------------------------------------------------------------
__device__ __forceinline__ unsigned f2tf32(float x) {
    unsigned r;
    asm("cvt.rna.tf32.f32 %0, %1;" : "=r"(r) : "f"(x));
    return r;
}

__device__ __forceinline__ void mma_tf32(float* c, const unsigned* a, const unsigned* b) {
    asm volatile(
        "mma.sync.aligned.m16n8k8.row.col.f32.tf32.tf32.f32 "
        "{%0,%1,%2,%3}, {%4,%5,%6,%7}, {%8,%9}, {%0,%1,%2,%3};"
        : "+f"(c[0]), "+f"(c[1]), "+f"(c[2]), "+f"(c[3])
        : "r"(a[0]), "r"(a[1]), "r"(a[2]), "r"(a[3]), "r"(b[0]), "r"(b[1]));
}

// ---------------------------------------------------------------------------
// tf32 tensor-core GEMM: C[M,N] = A[M,K] @ B[N,K]^T + bias[N]
// 128x128x32 block tile, 256 threads (8 warps), 64x32 warp tile.
// Tiles row-major [row][k], stride 36 (==4 mod 32) -> conflict-free LDS.
// ---------------------------------------------------------------------------
#define GBM 128
#define GBN 128
#define GBK 32
#define BKP 36

__global__ __launch_bounds__(256)
void gemm_tf32(const float* __restrict__ A, const float* __restrict__ B,
               const float* __restrict__ bias, float* __restrict__ C,
               int M, int N, int K)
{
    __shared__ unsigned As[GBM * BKP];
    __shared__ unsigned Bs[GBN * BKP];

    const int tid  = threadIdx.x;
    const int lane = tid & 31;
    const int wid  = tid >> 5;
    const int g    = lane >> 2;
    const int tg   = lane & 3;
    const int warp_m = (wid & 1) * 64;
    const int warp_n = (wid >> 1) * 32;
    const int bm = blockIdx.y * GBM;
    const int bn = blockIdx.x * GBN;

    float acc[4][4][4];
#pragma unroll
    for (int mt = 0; mt < 4; mt++)
#pragma unroll
        for (int nt = 0; nt < 4; nt++)
#pragma unroll
            for (int r = 0; r < 4; r++) acc[mt][nt][r] = 0.f;

    for (int k0 = 0; k0 < K; k0 += GBK) {
#pragma unroll
        for (int it = 0; it < 4; it++) {
            int lin = it * 256 + tid;
            int row = lin >> 3;
            int c4  = (lin & 7) << 2;
            float4 va = *(const float4*)(A + (size_t)(bm + row) * K + k0 + c4);
            uint4 ua = { f2tf32(va.x), f2tf32(va.y), f2tf32(va.z), f2tf32(va.w) };
            *(uint4*)(As + row * BKP + c4) = ua;
            float4 vb = *(const float4*)(B + (size_t)(bn + row) * K + k0 + c4);
            uint4 ub = { f2tf32(vb.x), f2tf32(vb.y), f2tf32(vb.z), f2tf32(vb.w) };
            *(uint4*)(Bs + row * BKP + c4) = ub;
        }
        __syncthreads();

#pragma unroll
        for (int kk = 0; kk < GBK; kk += 8) {
            unsigned afr[4][4];
#pragma unroll
            for (int mt = 0; mt < 4; mt++) {
                int r0 = warp_m + 16 * mt;
                afr[mt][0] = As[(r0 + g)     * BKP + kk + tg];
                afr[mt][1] = As[(r0 + g + 8) * BKP + kk + tg];
                afr[mt][2] = As[(r0 + g)     * BKP + kk + tg + 4];
                afr[mt][3] = As[(r0 + g + 8) * BKP + kk + tg + 4];
            }
            unsigned bfr[4][2];
#pragma unroll
            for (int nt = 0; nt < 4; nt++) {
                int n0 = warp_n + 8 * nt;
                bfr[nt][0] = Bs[(n0 + g) * BKP + kk + tg];
                bfr[nt][1] = Bs[(n0 + g) * BKP + kk + tg + 4];
            }
#pragma unroll
            for (int mt = 0; mt < 4; mt++)
#pragma unroll
                for (int nt = 0; nt < 4; nt++)
                    mma_tf32(acc[mt][nt], afr[mt], bfr[nt]);
        }
        __syncthreads();
    }

#pragma unroll
    for (int mt = 0; mt < 4; mt++) {
#pragma unroll
        for (int nt = 0; nt < 4; nt++) {
            int row0 = bm + warp_m + 16 * mt + g;
            int col0 = bn + warp_n + 8 * nt + 2 * tg;
            float bx = bias[col0], by = bias[col0 + 1];
            float2 lo = { acc[mt][nt][0] + bx, acc[mt][nt][1] + by };
            float2 hi = { acc[mt][nt][2] + bx, acc[mt][nt][3] + by };
            *(float2*)(C + (size_t)row0 * N + col0)       = lo;
            *(float2*)(C + (size_t)(row0 + 8) * N + col0) = hi;
        }
    }
}

// ---------------------------------------------------------------------------
// Flash attention, tf32 tensor cores.
// Block = 64 queries x pair-head x path. 128 threads (4 warps), warp = 16 rows.
// S = Q K^T via m16n8k8 (8 k-steps x 8 n-tiles); softmax fp32 in registers;
// P through per-warp smem; O = P V via m16n8k8 (8 k-steps x 16 n-tiles, Dv=128).
// Strides: Q/K/P 68 (==4 mod 32), V 136 (==8 mod 32) -> conflict-free.
// ---------------------------------------------------------------------------
#define AQ 68
#define AV 136
#define ATT_SMEM (64 * (3 * AQ + AV) * 4)   // 87040 bytes

__global__ __launch_bounds__(128)
void attn_tc(const float* __restrict__ qkv,
             float* __restrict__ O1, float* __restrict__ O2)
{
    extern __shared__ unsigned su[];
    unsigned* uQ = su;
    unsigned* uK = su + 64 * AQ;
    unsigned* uP = su + 2 * 64 * AQ;
    unsigned* uV = su + 3 * 64 * AQ;

    const int tid  = threadIdx.x;
    const int lane = tid & 31;
    const int wid  = tid >> 5;
    const int g    = lane >> 2;
    const int tg   = lane & 3;
    const int i0w  = wid * 16;          // warp's row base within the 64-row tile

    const int i0  = blockIdx.x * 64;
    const int p   = blockIdx.y;
    const int pt  = blockIdx.z;
    const int h   = 2 * p + pt;
    const int gp  = p / 10;
    const int qoff = h * 64;
    const int koff = 2560 + (2 * gp + pt) * 64;
    const int voff = 2816 + 2 * gp * 64;        // v1|v2: 128 contiguous floats
    float* Oout = pt ? O2 : O1;

    // ---- Load Q tile (64x64), scale, convert to tf32 ----
#pragma unroll
    for (int it = 0; it < 8; it++) {
        int lin = it * 128 + tid;       // 0..1023
        int row = lin >> 4;
        int c4  = (lin & 15) << 2;
        float4 v = *(const float4*)(qkv + (size_t)(i0 + row) * QKV_N + qoff + c4);
        uint4 u = { f2tf32(v.x * SCALE_F), f2tf32(v.y * SCALE_F),
                    f2tf32(v.z * SCALE_F), f2tf32(v.w * SCALE_F) };
        *(uint4*)(uQ + row * AQ + c4) = u;
    }
    __syncthreads();

    // ---- Preload Q fragments (reused every iteration) ----
    unsigned qf[8][4];
#pragma unroll
    for (int k = 0; k < 8; k++) {
        int kk8 = k * 8;
        qf[k][0] = uQ[(i0w + g)     * AQ + kk8 + tg];
        qf[k][1] = uQ[(i0w + g + 8) * AQ + kk8 + tg];
        qf[k][2] = uQ[(i0w + g)     * AQ + kk8 + tg + 4];
        qf[k][3] = uQ[(i0w + g + 8) * AQ + kk8 + tg + 4];
    }

    float m0 = -1e30f, m1 = -1e30f, l0 = 0.f, l1 = 0.f;
    float oacc[16][4];
#pragma unroll
    for (int nt = 0; nt < 16; nt++)
#pragma unroll
        for (int r = 0; r < 4; r++) oacc[nt][r] = 0.f;

    for (int j0 = 0; j0 <= i0; j0 += 64) {
        __syncthreads();    // previous iteration's K/V reads complete

        // ---- Load K tile (64x64) as tf32 ----
#pragma unroll
        for (int it = 0; it < 8; it++) {
            int lin = it * 128 + tid;
            int row = lin >> 4;
            int c4  = (lin & 15) << 2;
            float4 v = *(const float4*)(qkv + (size_t)(j0 + row) * QKV_N + koff + c4);
            uint4 u = { f2tf32(v.x), f2tf32(v.y), f2tf32(v.z), f2tf32(v.w) };
            *(uint4*)(uK + row * AQ + c4) = u;
        }
        // ---- Load V tile (64x128) as tf32 ----
#pragma unroll
        for (int it = 0; it < 16; it++) {
            int lin = it * 128 + tid;       // 0..2047
            int row = lin >> 5;
            int c4  = (lin & 31) << 2;
            float4 v = *(const float4*)(qkv + (size_t)(j0 + row) * QKV_N + voff + c4);
            uint4 u = { f2tf32(v.x), f2tf32(v.y), f2tf32(v.z), f2tf32(v.w) };
            *(uint4*)(uV + row * AV + c4) = u;
        }
        __syncthreads();

        // ---- S = Q K^T : 8 n-tiles of 8 cols ----
        float sacc[8][4];
#pragma unroll
        for (int nt = 0; nt < 8; nt++)
#pragma unroll
            for (int r = 0; r < 4; r++) sacc[nt][r] = 0.f;

#pragma unroll
        for (int k = 0; k < 8; k++) {
            int kk8 = k * 8;
#pragma unroll
            for (int nt = 0; nt < 8; nt++) {
                unsigned bf[2];
                bf[0] = uK[(nt * 8 + g) * AQ + kk8 + tg];
                bf[1] = uK[(nt * 8 + g) * AQ + kk8 + tg + 4];
                mma_tf32(sacc[nt], qf[k], bf);
            }
        }

        // ---- Causal mask on diagonal block ----
        if (j0 == i0) {
            int r0 = i0w + g, r1 = r0 + 8;
#pragma unroll
            for (int nt = 0; nt < 8; nt++) {
                int c0 = nt * 8 + 2 * tg;
                if (c0     > r0) sacc[nt][0] = -1e30f;
                if (c0 + 1 > r0) sacc[nt][1] = -1e30f;
                if (c0     > r1) sacc[nt][2] = -1e30f;
                if (c0 + 1 > r1) sacc[nt][3] = -1e30f;
            }
        }

        // ---- Online softmax (thread rows g and g+8; quad holds full row) ----
        float tm0 = -1e30f, tm1 = -1e30f;
#pragma unroll
        for (int nt = 0; nt < 8; nt++) {
            tm0 = fmaxf(tm0, fmaxf(sacc[nt][0], sacc[nt][1]));
            tm1 = fmaxf(tm1, fmaxf(sacc[nt][2], sacc[nt][3]));
        }
        tm0 = fmaxf(tm0, __shfl_xor_sync(0xffffffffu, tm0, 1));
        tm0 = fmaxf(tm0, __shfl_xor_sync(0xffffffffu, tm0, 2));
        tm1 = fmaxf(tm1, __shfl_xor_sync(0xffffffffu, tm1, 1));
        tm1 = fmaxf(tm1, __shfl_xor_sync(0xffffffffu, tm1, 2));

        float mn0 = fmaxf(m0, tm0), sc0 = __expf(m0 - mn0);
        float mn1 = fmaxf(m1, tm1), sc1 = __expf(m1 - mn1);

        float rs0 = 0.f, rs1 = 0.f;
#pragma unroll
        for (int nt = 0; nt < 8; nt++) {
            // round to tf32 and accumulate the ROUNDED value so P/l stay consistent
            unsigned u0 = f2tf32(__expf(sacc[nt][0] - mn0));
            unsigned u1 = f2tf32(__expf(sacc[nt][1] - mn0));
            unsigned u2 = f2tf32(__expf(sacc[nt][2] - mn1));
            unsigned u3 = f2tf32(__expf(sacc[nt][3] - mn1));
            rs0 += __uint_as_float(u0) + __uint_as_float(u1);
            rs1 += __uint_as_float(u2) + __uint_as_float(u3);
            uint2 lo = { u0, u1 }, hi = { u2, u3 };
            *(uint2*)(uP + (i0w + g)     * AQ + nt * 8 + 2 * tg) = lo;
            *(uint2*)(uP + (i0w + g + 8) * AQ + nt * 8 + 2 * tg) = hi;
        }
        rs0 += __shfl_xor_sync(0xffffffffu, rs0, 1);
        rs0 += __shfl_xor_sync(0xffffffffu, rs0, 2);
        rs1 += __shfl_xor_sync(0xffffffffu, rs1, 1);
        rs1 += __shfl_xor_sync(0xffffffffu, rs1, 2);

        l0 = l0 * sc0 + rs0;  m0 = mn0;
        l1 = l1 * sc1 + rs1;  m1 = mn1;
#pragma unroll
        for (int nt = 0; nt < 16; nt++) {
            oacc[nt][0] *= sc0; oacc[nt][1] *= sc0;
            oacc[nt][2] *= sc1; oacc[nt][3] *= sc1;
        }
        __syncwarp();   // P visible within warp (each warp reads only its own rows)

        // ---- O += P V : 16 n-tiles over Dv=128 ----
#pragma unroll
        for (int k = 0; k < 8; k++) {
            int kk8 = k * 8;
            unsigned pf[4];
            pf[0] = uP[(i0w + g)     * AQ + kk8 + tg];
            pf[1] = uP[(i0w + g + 8) * AQ + kk8 + tg];
            pf[2] = uP[(i0w + g)     * AQ + kk8 + tg + 4];
            pf[3] = uP[(i0w + g + 8) * AQ + kk8 + tg + 4];
#pragma unroll
            for (int nt = 0; nt < 16; nt++) {
                unsigned bf[2];
                bf[0] = uV[(kk8 + tg)     * AV + nt * 8 + g];
                bf[1] = uV[(kk8 + tg + 4) * AV + nt * 8 + g];
                mma_tf32(oacc[nt], pf, bf);
            }
        }
    }

    // ---- Epilogue: normalize, store ----
    float inv0 = 1.f / l0, inv1 = 1.f / l1;
    int row0 = i0 + i0w + g;
#pragma unroll
    for (int nt = 0; nt < 16; nt++) {
        int col = p * 128 + nt * 8 + 2 * tg;
        float2 lo = { oacc[nt][0] * inv0, oacc[nt][1] * inv0 };
        float2 hi = { oacc[nt][2] * inv1, oacc[nt][3] * inv1 };
        *(float2*)(Oout + (size_t)row0 * HID + col)       = lo;
        *(float2*)(Oout + (size_t)(row0 + 8) * HID + col) = hi;
    }
}

// ---------------------------------------------------------------------------
// lambda_full = exp(sum lq1*lk1) - exp(sum lq2*lk2) + LAMBDA_INIT
// ---------------------------------------------------------------------------
__global__ void lambda_kernel(const float* __restrict__ lq1, const float* __restrict__ lk1,
                              const float* __restrict__ lq2, const float* __restrict__ lk2)
{
    __shared__ float sa[64], sb[64];
    int t = threadIdx.x;
    sa[t] = lq1[t] * lk1[t];
    sb[t] = lq2[t] * lk2[t];
    __syncthreads();
    if (t == 0) {
        float s1 = 0.f, s2 = 0.f;
        for (int i = 0; i < 64; i++) { s1 += sa[i]; s2 += sb[i]; }
        const float lambda_init = 0.8f - 0.6f * expf(-0.3f * 17.0f);
        g_lambda = expf(s1) - expf(s2) + lambda_init;
    }
}

// ---------------------------------------------------------------------------
// Combine: a = O1 - lambda*O2 ; rmsnorm over 128 dims ; * subln_w * (1-l_init)
// ---------------------------------------------------------------------------
__global__ __launch_bounds__(128)
void combine_kernel(const float* __restrict__ O1, const float* __restrict__ O2,
                    const float* __restrict__ subln, float* __restrict__ Aout)
{
    const int sp = blockIdx.x;
    const int s  = sp / NPAIR;
    const int pp = sp - s * NPAIR;
    const int c  = threadIdx.x;
    const size_t idx = (size_t)s * HID + pp * 128 + c;

    const float lam = g_lambda;
    const float a = O1[idx] - lam * O2[idx];

    float ss = a * a;
#pragma unroll
    for (int off = 16; off > 0; off >>= 1)
        ss += __shfl_xor_sync(0xffffffffu, ss, off);

    __shared__ float ws[4];
    __shared__ float tot;
    if ((c & 31) == 0) ws[c >> 5] = ss;
    __syncthreads();
    if (c == 0) tot = ws[0] + ws[1] + ws[2] + ws[3];
    __syncthreads();

    const float lambda_init = 0.8f - 0.6f * expf(-0.3f * 17.0f);
    const float rms = rsqrtf(tot * (1.f / 128.f) + 1e-5f);
    Aout[idx] = subln[c] * a * rms * (1.f - lambda_init);
}

// ---------------------------------------------------------------------------
// Launch
// ---------------------------------------------------------------------------
extern "C" void kernel_launch(void* const* d_in, const int* in_sizes, int n_in,
                              void* d_out, int out_size)
{
    const float* hidden = (const float*)d_in[0];
    const float* Wqkv_w = (const float*)d_in[1];
    const float* Wqkv_b = (const float*)d_in[2];
    const float* out_w  = (const float*)d_in[3];
    const float* out_b  = (const float*)d_in[4];
    const float* lq1    = (const float*)d_in[5];
    const float* lk1    = (const float*)d_in[6];
    const float* lq2    = (const float*)d_in[7];
    const float* lk2    = (const float*)d_in[8];
    const float* subln  = (const float*)d_in[9];
    float* out = (float*)d_out;

    float *qkv, *O1, *O2, *attn;
    cudaGetSymbolAddress((void**)&qkv,  g_qkv);
    cudaGetSymbolAddress((void**)&O1,   g_O1);
    cudaGetSymbolAddress((void**)&O2,   g_O2);
    cudaGetSymbolAddress((void**)&attn, g_attn);

    cudaFuncSetAttribute(attn_tc,
                         cudaFuncAttributeMaxDynamicSharedMemorySize, ATT_SMEM);

    // 1) QKV projection (tf32 tensor cores)
    {
        dim3 grid(QKV_N / GBN, S_LEN / GBM);
        gemm_tf32<<<grid, 256>>>(hidden, Wqkv_w, Wqkv_b, qkv, S_LEN, QKV_N, HID);
    }

    // 2) lambda scalar
    lambda_kernel<<<1, 64>>>(lq1, lk1, lq2, lk2);

    // 3) Flash attention (tf32 tensor cores), both paths, all 20 pair-heads
    {
        dim3 grid(S_LEN / 64, NPAIR, 2);
        attn_tc<<<grid, 128, ATT_SMEM>>>(qkv, O1, O2);
    }

    // 4) Differential combine + RMSNorm
    combine_kernel<<<S_LEN * NPAIR, 128>>>(O1, O2, subln, attn);

    // 5) Output projection (tf32 tensor cores)
    {
        dim3 grid(HID / GBN, S_LEN / GBM);
        gemm_tf32<<<grid, 256>>>(attn, out_w, out_b, out, S_LEN, HID, HID);
    }
}

// round 5
// speedup vs baseline: 3.4263x; 1.0388x over previous
#include <cuda_runtime.h>
#include <math.h>

// ---------------------------------------------------------------------------
// Problem constants
// ---------------------------------------------------------------------------
#define S_LEN  2048
#define HID    2560
#define QKV_N  3072          // NH*D + 2*NKV*D
#define NPAIR  20            // NH/2
#define SCALE_F 0.125f       // 1/sqrt(64)

// ---------------------------------------------------------------------------
// Scratch (no allocations allowed -> __device__ globals)
// ---------------------------------------------------------------------------
__device__ float g_qkv [S_LEN * QKV_N];
__device__ float g_attn[S_LEN * HID];
__device__ float g_lambda;

// ---------------------------------------------------------------------------
// tf32 helpers
// ---------------------------------------------------------------------------
__device__ __forceinline__ unsigned f2tf32(float x) {
    unsigned r;
    asm("cvt.rna.tf32.f32 %0, %1;" : "=r"(r) : "f"(x));
    return r;
}

__device__ __forceinline__ void mma_tf32(float* c, const unsigned* a, const unsigned* b) {
    asm volatile(
        "mma.sync.aligned.m16n8k8.row.col.f32.tf32.tf32.f32 "
        "{%0,%1,%2,%3}, {%4,%5,%6,%7}, {%8,%9}, {%0,%1,%2,%3};"
        : "+f"(c[0]), "+f"(c[1]), "+f"(c[2]), "+f"(c[3])
        : "r"(a[0]), "r"(a[1]), "r"(a[2]), "r"(a[3]), "r"(b[0]), "r"(b[1]));
}

// ---------------------------------------------------------------------------
// tf32 GEMM with 2-stage double-buffered prefetch.
// C[M,N] = A[M,K] @ B[N,K]^T + bias[N]
// 128x128 block tile, GBK=16, 256 threads (8 warps), 64x32 warp tile.
// Tiles row-major [row][k], stride 20 (20g+tg mod 32 is a permutation
// -> conflict-free fragment LDS; STS.128 worst case 2-way).
// ---------------------------------------------------------------------------
#define GBK 16
#define KSTR 20

__global__ __launch_bounds__(256, 2)
void gemm_tf32(const float* __restrict__ A, const float* __restrict__ B,
               const float* __restrict__ bias, float* __restrict__ C,
               int M, int N, int K)
{
    __shared__ unsigned As[2][128 * KSTR];
    __shared__ unsigned Bs[2][128 * KSTR];

    const int tid  = threadIdx.x;
    const int lane = tid & 31;
    const int wid  = tid >> 5;
    const int g    = lane >> 2;
    const int tg   = lane & 3;
    const int warp_m = (wid & 1) * 64;
    const int warp_n = (wid >> 1) * 32;
    const int bm = blockIdx.y * 128;
    const int bn = blockIdx.x * 128;

    // load coords: A/B tile = 128 rows x 16 floats = 512 float4; 2 per thread
    const int r0l = tid >> 2;            // rows for lin=tid        (0..63)
    const int r1l = (tid + 256) >> 2;    // rows for lin=tid+256    (64..127)
    const int c4l = (tid & 3) << 2;

    float acc[4][4][4];
#pragma unroll
    for (int mt = 0; mt < 4; mt++)
#pragma unroll
        for (int nt = 0; nt < 4; nt++)
#pragma unroll
            for (int r = 0; r < 4; r++) acc[mt][nt][r] = 0.f;

    float4 pa0, pa1, pb0, pb1;

    // ---- preload stage 0 ----
    pa0 = *(const float4*)(A + (size_t)(bm + r0l) * K + c4l);
    pa1 = *(const float4*)(A + (size_t)(bm + r1l) * K + c4l);
    pb0 = *(const float4*)(B + (size_t)(bn + r0l) * K + c4l);
    pb1 = *(const float4*)(B + (size_t)(bn + r1l) * K + c4l);
    {
        uint4 u;
        u.x = f2tf32(pa0.x); u.y = f2tf32(pa0.y); u.z = f2tf32(pa0.z); u.w = f2tf32(pa0.w);
        *(uint4*)(&As[0][r0l * KSTR + c4l]) = u;
        u.x = f2tf32(pa1.x); u.y = f2tf32(pa1.y); u.z = f2tf32(pa1.z); u.w = f2tf32(pa1.w);
        *(uint4*)(&As[0][r1l * KSTR + c4l]) = u;
        u.x = f2tf32(pb0.x); u.y = f2tf32(pb0.y); u.z = f2tf32(pb0.z); u.w = f2tf32(pb0.w);
        *(uint4*)(&Bs[0][r0l * KSTR + c4l]) = u;
        u.x = f2tf32(pb1.x); u.y = f2tf32(pb1.y); u.z = f2tf32(pb1.z); u.w = f2tf32(pb1.w);
        *(uint4*)(&Bs[0][r1l * KSTR + c4l]) = u;
    }
    __syncthreads();

    int buf = 0;
    for (int k0 = 0; k0 < K; k0 += GBK) {
        const bool more = (k0 + GBK) < K;
        if (more) {
            const float* Ak = A + k0 + GBK + c4l;
            const float* Bk = B + k0 + GBK + c4l;
            pa0 = *(const float4*)(Ak + (size_t)(bm + r0l) * K);
            pa1 = *(const float4*)(Ak + (size_t)(bm + r1l) * K);
            pb0 = *(const float4*)(Bk + (size_t)(bn + r0l) * K);
            pb1 = *(const float4*)(Bk + (size_t)(bn + r1l) * K);
        }

        // ---- MMAs on current stage ----
#pragma unroll
        for (int kk = 0; kk < GBK; kk += 8) {
            unsigned afr[4][4];
#pragma unroll
            for (int mt = 0; mt < 4; mt++) {
                int r0 = warp_m + 16 * mt;
                afr[mt][0] = As[buf][(r0 + g)     * KSTR + kk + tg];
                afr[mt][1] = As[buf][(r0 + g + 8) * KSTR + kk + tg];
                afr[mt][2] = As[buf][(r0 + g)     * KSTR + kk + tg + 4];
                afr[mt][3] = As[buf][(r0 + g + 8) * KSTR + kk + tg + 4];
            }
            unsigned bfr[4][2];
#pragma unroll
            for (int nt = 0; nt < 4; nt++) {
                int n0 = warp_n + 8 * nt;
                bfr[nt][0] = Bs[buf][(n0 + g) * KSTR + kk + tg];
                bfr[nt][1] = Bs[buf][(n0 + g) * KSTR + kk + tg + 4];
            }
#pragma unroll
            for (int mt = 0; mt < 4; mt++)
#pragma unroll
                for (int nt = 0; nt < 4; nt++)
                    mma_tf32(acc[mt][nt], afr[mt], bfr[nt]);
        }

        if (more) {
            uint4 u;
            u.x = f2tf32(pa0.x); u.y = f2tf32(pa0.y); u.z = f2tf32(pa0.z); u.w = f2tf32(pa0.w);
            *(uint4*)(&As[buf ^ 1][r0l * KSTR + c4l]) = u;
            u.x = f2tf32(pa1.x); u.y = f2tf32(pa1.y); u.z = f2tf32(pa1.z); u.w = f2tf32(pa1.w);
            *(uint4*)(&As[buf ^ 1][r1l * KSTR + c4l]) = u;
            u.x = f2tf32(pb0.x); u.y = f2tf32(pb0.y); u.z = f2tf32(pb0.z); u.w = f2tf32(pb0.w);
            *(uint4*)(&Bs[buf ^ 1][r0l * KSTR + c4l]) = u;
            u.x = f2tf32(pb1.x); u.y = f2tf32(pb1.y); u.z = f2tf32(pb1.z); u.w = f2tf32(pb1.w);
            *(uint4*)(&Bs[buf ^ 1][r1l * KSTR + c4l]) = u;
        }
        __syncthreads();
        buf ^= 1;
    }

    // ---- epilogue ----
#pragma unroll
    for (int mt = 0; mt < 4; mt++) {
#pragma unroll
        for (int nt = 0; nt < 4; nt++) {
            int row0 = bm + warp_m + 16 * mt + g;
            int col0 = bn + warp_n + 8 * nt + 2 * tg;
            float bx = bias[col0], by = bias[col0 + 1];
            float2 lo = { acc[mt][nt][0] + bx, acc[mt][nt][1] + by };
            float2 hi = { acc[mt][nt][2] + bx, acc[mt][nt][3] + by };
            *(float2*)(C + (size_t)row0 * N + col0)       = lo;
            *(float2*)(C + (size_t)(row0 + 8) * N + col0) = hi;
        }
    }
}

// ---------------------------------------------------------------------------
// Fused differential flash attention, tf32 tensor cores.
// Block = 64 queries x pair-head, BOTH paths: warps 0-3 path0, warps 4-7 path1
// (paths share the V tile). After the flash loop, path-1 warps hand their
// normalized O2 through smem; path-0 warps compute O1 - lambda*O2, RMSNorm
// over the 128-dim pair, scale, and write g_attn directly.
// smem regions (words): QP 2x64x68 | K 2x64x68 (reused as xchg) | V 64x136.
// ---------------------------------------------------------------------------
#define AQ 68
#define AV 136
#define XST 132
#define ATT_SMEM ((4 * 64 * AQ + 64 * AV) * 4)   // 104448 bytes

__global__ __launch_bounds__(256)
void attn_fused(const float* __restrict__ qkv, const float* __restrict__ subln,
                float* __restrict__ Aout)
{
    extern __shared__ unsigned su[];
    unsigned* uQP = su;                    // per path: 64*AQ ; Q then P
    unsigned* uK  = su + 2 * 64 * AQ;      // per path: 64*AQ ; later exchange
    unsigned* uV  = su + 4 * 64 * AQ;      // 64*AV
    float* xbuf = (float*)uK;              // 64 x XST at combine time

    const int tid  = threadIdx.x;
    const int lane = tid & 31;
    const int wid  = tid >> 5;
    const int g    = lane >> 2;
    const int tg   = lane & 3;
    const int pth  = wid >> 2;             // warp's path (threads 0-127 <-> 0)
    const int i0w  = (wid & 3) * 16;
    const int tid2 = tid & 127;

    const int i0 = blockIdx.x * 64;
    const int p  = blockIdx.y;
    const int gp = p / 10;
    const int qoff = (2 * p + pth) * 64;
    const int koff = 2560 + (2 * gp + pth) * 64;
    const int voff = 2816 + 2 * gp * 64;

    unsigned* uQp = uQP + pth * (64 * AQ);
    unsigned* uKp = uK  + pth * (64 * AQ);

    // ---- Load this path's Q tile (64x64), scale, tf32 ----
#pragma unroll
    for (int it = 0; it < 8; it++) {
        int lin = it * 128 + tid2;
        int row = lin >> 4;
        int c4  = (lin & 15) << 2;
        float4 v = *(const float4*)(qkv + (size_t)(i0 + row) * QKV_N + qoff + c4);
        uint4 u = { f2tf32(v.x * SCALE_F), f2tf32(v.y * SCALE_F),
                    f2tf32(v.z * SCALE_F), f2tf32(v.w * SCALE_F) };
        *(uint4*)(uQp + row * AQ + c4) = u;
    }
    __syncthreads();

    // ---- Preload Q fragments (Q smem dead afterwards; region reused for P) ----
    unsigned qf[8][4];
#pragma unroll
    for (int k = 0; k < 8; k++) {
        int kk8 = k * 8;
        qf[k][0] = uQp[(i0w + g)     * AQ + kk8 + tg];
        qf[k][1] = uQp[(i0w + g + 8) * AQ + kk8 + tg];
        qf[k][2] = uQp[(i0w + g)     * AQ + kk8 + tg + 4];
        qf[k][3] = uQp[(i0w + g + 8) * AQ + kk8 + tg + 4];
    }

    float m0 = -1e30f, m1 = -1e30f, l0 = 0.f, l1 = 0.f;
    float oacc[16][4];
#pragma unroll
    for (int nt = 0; nt < 16; nt++)
#pragma unroll
        for (int r = 0; r < 4; r++) oacc[nt][r] = 0.f;

    for (int j0 = 0; j0 <= i0; j0 += 64) {
        __syncthreads();    // prior iteration's K/V reads complete

        // ---- this path's K tile (64x64) ----
#pragma unroll
        for (int it = 0; it < 8; it++) {
            int lin = it * 128 + tid2;
            int row = lin >> 4;
            int c4  = (lin & 15) << 2;
            float4 v = *(const float4*)(qkv + (size_t)(j0 + row) * QKV_N + koff + c4);
            uint4 u = { f2tf32(v.x), f2tf32(v.y), f2tf32(v.z), f2tf32(v.w) };
            *(uint4*)(uKp + row * AQ + c4) = u;
        }
        // ---- shared V tile (64x128), all 256 threads ----
#pragma unroll
        for (int it = 0; it < 8; it++) {
            int lin = it * 256 + tid;
            int row = lin >> 5;
            int c4  = (lin & 31) << 2;
            float4 v = *(const float4*)(qkv + (size_t)(j0 + row) * QKV_N + voff + c4);
            uint4 u = { f2tf32(v.x), f2tf32(v.y), f2tf32(v.z), f2tf32(v.w) };
            *(uint4*)(uV + row * AV + c4) = u;
        }
        __syncthreads();

        // ---- S = Q K^T ----
        float sacc[8][4];
#pragma unroll
        for (int nt = 0; nt < 8; nt++)
#pragma unroll
            for (int r = 0; r < 4; r++) sacc[nt][r] = 0.f;

#pragma unroll
        for (int k = 0; k < 8; k++) {
            int kk8 = k * 8;
#pragma unroll
            for (int nt = 0; nt < 8; nt++) {
                unsigned bf[2];
                bf[0] = uKp[(nt * 8 + g) * AQ + kk8 + tg];
                bf[1] = uKp[(nt * 8 + g) * AQ + kk8 + tg + 4];
                mma_tf32(sacc[nt], qf[k], bf);
            }
        }

        // ---- causal mask on diagonal block ----
        if (j0 == i0) {
            int r0 = i0w + g, r1 = r0 + 8;
#pragma unroll
            for (int nt = 0; nt < 8; nt++) {
                int c0 = nt * 8 + 2 * tg;
                if (c0     > r0) sacc[nt][0] = -1e30f;
                if (c0 + 1 > r0) sacc[nt][1] = -1e30f;
                if (c0     > r1) sacc[nt][2] = -1e30f;
                if (c0 + 1 > r1) sacc[nt][3] = -1e30f;
            }
        }

        // ---- online softmax (rows g, g+8; quad spans the row) ----
        float tm0 = -1e30f, tm1 = -1e30f;
#pragma unroll
        for (int nt = 0; nt < 8; nt++) {
            tm0 = fmaxf(tm0, fmaxf(sacc[nt][0], sacc[nt][1]));
            tm1 = fmaxf(tm1, fmaxf(sacc[nt][2], sacc[nt][3]));
        }
        tm0 = fmaxf(tm0, __shfl_xor_sync(0xffffffffu, tm0, 1));
        tm0 = fmaxf(tm0, __shfl_xor_sync(0xffffffffu, tm0, 2));
        tm1 = fmaxf(tm1, __shfl_xor_sync(0xffffffffu, tm1, 1));
        tm1 = fmaxf(tm1, __shfl_xor_sync(0xffffffffu, tm1, 2));

        float mn0 = fmaxf(m0, tm0), sc0 = __expf(m0 - mn0);
        float mn1 = fmaxf(m1, tm1), sc1 = __expf(m1 - mn1);

        float rs0 = 0.f, rs1 = 0.f;
#pragma unroll
        for (int nt = 0; nt < 8; nt++) {
            unsigned u0 = f2tf32(__expf(sacc[nt][0] - mn0));
            unsigned u1 = f2tf32(__expf(sacc[nt][1] - mn0));
            unsigned u2 = f2tf32(__expf(sacc[nt][2] - mn1));
            unsigned u3 = f2tf32(__expf(sacc[nt][3] - mn1));
            rs0 += __uint_as_float(u0) + __uint_as_float(u1);
            rs1 += __uint_as_float(u2) + __uint_as_float(u3);
            uint2 lo = { u0, u1 }, hi = { u2, u3 };
            *(uint2*)(uQp + (i0w + g)     * AQ + nt * 8 + 2 * tg) = lo;
            *(uint2*)(uQp + (i0w + g + 8) * AQ + nt * 8 + 2 * tg) = hi;
        }
        rs0 += __shfl_xor_sync(0xffffffffu, rs0, 1);
        rs0 += __shfl_xor_sync(0xffffffffu, rs0, 2);
        rs1 += __shfl_xor_sync(0xffffffffu, rs1, 1);
        rs1 += __shfl_xor_sync(0xffffffffu, rs1, 2);

        l0 = l0 * sc0 + rs0;  m0 = mn0;
        l1 = l1 * sc1 + rs1;  m1 = mn1;
#pragma unroll
        for (int nt = 0; nt < 16; nt++) {
            oacc[nt][0] *= sc0; oacc[nt][1] *= sc0;
            oacc[nt][2] *= sc1; oacc[nt][3] *= sc1;
        }
        __syncwarp();   // P rows are per-warp private

        // ---- O += P V ----
#pragma unroll
        for (int k = 0; k < 8; k++) {
            int kk8 = k * 8;
            unsigned pf[4];
            pf[0] = uQp[(i0w + g)     * AQ + kk8 + tg];
            pf[1] = uQp[(i0w + g + 8) * AQ + kk8 + tg];
            pf[2] = uQp[(i0w + g)     * AQ + kk8 + tg + 4];
            pf[3] = uQp[(i0w + g + 8) * AQ + kk8 + tg + 4];
#pragma unroll
            for (int nt = 0; nt < 16; nt++) {
                unsigned bf[2];
                bf[0] = uV[(kk8 + tg)     * AV + nt * 8 + g];
                bf[1] = uV[(kk8 + tg + 4) * AV + nt * 8 + g];
                mma_tf32(oacc[nt], pf, bf);
            }
        }
    }

    // ---- combine: path1 exports normalized O2; path0 does diff + RMSNorm ----
    const float inv0 = 1.f / l0, inv1 = 1.f / l1;
    __syncthreads();                       // K region now dead -> exchange buffer

    if (pth == 1) {
#pragma unroll
        for (int nt = 0; nt < 16; nt++) {
            int col = nt * 8 + 2 * tg;
            float2 lo = { oacc[nt][0] * inv0, oacc[nt][1] * inv0 };
            float2 hi = { oacc[nt][2] * inv1, oacc[nt][3] * inv1 };
            *(float2*)(xbuf + (i0w + g)     * XST + col) = lo;
            *(float2*)(xbuf + (i0w + g + 8) * XST + col) = hi;
        }
    }
    __syncthreads();

    if (pth == 0) {
        const float lam = g_lambda;
        const float li  = 0.8f - 0.6f * expf(-0.3f * 17.0f);
        float ss0 = 0.f, ss1 = 0.f;
#pragma unroll
        for (int nt = 0; nt < 16; nt++) {
            int col = nt * 8 + 2 * tg;
            float2 o2a = *(float2*)(xbuf + (i0w + g)     * XST + col);
            float2 o2b = *(float2*)(xbuf + (i0w + g + 8) * XST + col);
            float v0 = oacc[nt][0] * inv0 - lam * o2a.x;
            float v1 = oacc[nt][1] * inv0 - lam * o2a.y;
            float v2 = oacc[nt][2] * inv1 - lam * o2b.x;
            float v3 = oacc[nt][3] * inv1 - lam * o2b.y;
            oacc[nt][0] = v0; oacc[nt][1] = v1; oacc[nt][2] = v2; oacc[nt][3] = v3;
            ss0 += v0 * v0 + v1 * v1;
            ss1 += v2 * v2 + v3 * v3;
        }
        ss0 += __shfl_xor_sync(0xffffffffu, ss0, 1);
        ss0 += __shfl_xor_sync(0xffffffffu, ss0, 2);
        ss1 += __shfl_xor_sync(0xffffffffu, ss1, 1);
        ss1 += __shfl_xor_sync(0xffffffffu, ss1, 2);

        const float rms0 = rsqrtf(ss0 * (1.f / 128.f) + 1e-5f) * (1.f - li);
        const float rms1 = rsqrtf(ss1 * (1.f / 128.f) + 1e-5f) * (1.f - li);
        const int row0 = i0 + i0w + g;
#pragma unroll
        for (int nt = 0; nt < 16; nt++) {
            int col = nt * 8 + 2 * tg;
            float w0 = subln[col], w1 = subln[col + 1];
            float2 lo = { oacc[nt][0] * rms0 * w0, oacc[nt][1] * rms0 * w1 };
            float2 hi = { oacc[nt][2] * rms1 * w0, oacc[nt][3] * rms1 * w1 };
            *(float2*)(Aout + (size_t)row0 * HID + p * 128 + col)       = lo;
            *(float2*)(Aout + (size_t)(row0 + 8) * HID + p * 128 + col) = hi;
        }
    }
}

// ---------------------------------------------------------------------------
// lambda_full = exp(sum lq1*lk1) - exp(sum lq2*lk2) + LAMBDA_INIT
// ---------------------------------------------------------------------------
__global__ void lambda_kernel(const float* __restrict__ lq1, const float* __restrict__ lk1,
                              const float* __restrict__ lq2, const float* __restrict__ lk2)
{
    __shared__ float sa[64], sb[64];
    int t = threadIdx.x;
    sa[t] = lq1[t] * lk1[t];
    sb[t] = lq2[t] * lk2[t];
    __syncthreads();
    if (t == 0) {
        float s1 = 0.f, s2 = 0.f;
        for (int i = 0; i < 64; i++) { s1 += sa[i]; s2 += sb[i]; }
        const float lambda_init = 0.8f - 0.6f * expf(-0.3f * 17.0f);
        g_lambda = expf(s1) - expf(s2) + lambda_init;
    }
}

// ---------------------------------------------------------------------------
// Launch
// ---------------------------------------------------------------------------
extern "C" void kernel_launch(void* const* d_in, const int* in_sizes, int n_in,
                              void* d_out, int out_size)
{
    const float* hidden = (const float*)d_in[0];
    const float* Wqkv_w = (const float*)d_in[1];
    const float* Wqkv_b = (const float*)d_in[2];
    const float* out_w  = (const float*)d_in[3];
    const float* out_b  = (const float*)d_in[4];
    const float* lq1    = (const float*)d_in[5];
    const float* lk1    = (const float*)d_in[6];
    const float* lq2    = (const float*)d_in[7];
    const float* lk2    = (const float*)d_in[8];
    const float* subln  = (const float*)d_in[9];
    float* out = (float*)d_out;

    float *qkv, *attn;
    cudaGetSymbolAddress((void**)&qkv,  g_qkv);
    cudaGetSymbolAddress((void**)&attn, g_attn);

    cudaFuncSetAttribute(attn_fused,
                         cudaFuncAttributeMaxDynamicSharedMemorySize, ATT_SMEM);

    // 1) QKV projection (tf32, double-buffered)
    {
        dim3 grid(QKV_N / 128, S_LEN / 128);
        gemm_tf32<<<grid, 256>>>(hidden, Wqkv_w, Wqkv_b, qkv, S_LEN, QKV_N, HID);
    }

    // 2) lambda scalar
    lambda_kernel<<<1, 64>>>(lq1, lk1, lq2, lk2);

    // 3) Fused differential attention + combine + RMSNorm
    {
        dim3 grid(S_LEN / 64, NPAIR);
        attn_fused<<<grid, 256, ATT_SMEM>>>(qkv, subln, attn);
    }

    // 4) Output projection (tf32, double-buffered)
    {
        dim3 grid(HID / 128, S_LEN / 128);
        gemm_tf32<<<grid, 256>>>(attn, out_w, out_b, out, S_LEN, HID, HID);
    }
}